// round 6
// baseline (speedup 1.0000x reference)
#include <cuda_runtime.h>
#include <cuda_bf16.h>
#include <math.h>

// Problem constants
#define BATCH   256
#define IN_CH   1152
#define OUT_CH  10
#define OUT_U   16
#define K_DIM   8
#define OUD     160              // OUT_CH*OUT_U
#define UH_BSTRIDE (IN_CH*OUD)   // 184320: stride of u_hat per batch

// Scratch (device globals — allocation-free)
__device__ float g_uhat[(size_t)BATCH * IN_CH * OUD]; // [b][i][o*16+u]  (~189MB)
__device__ float g_s[BATCH * OUD];                    // iter-0 s (c = 0.1 fused)
__device__ float g_v[BATCH * OUD];                    // squashed v
__device__ float g_blog[IN_CH * OUT_CH];              // routing logits b
__device__ float g_c[IN_CH * OUT_CH];                 // softmax(b)

// ---------------------------------------------------------------------------
// Zero the per-iteration state (must run every launch: graph replays!)
__global__ void k_init() {
    int t = blockIdx.x * blockDim.x + threadIdx.x;
    if (t < BATCH * OUD) g_s[t] = 0.0f;
    if (t < IN_CH * OUT_CH) g_blog[t] = 0.0f;
}

// ---------------------------------------------------------------------------
// u_hat producer + fused iter-0 s accumulation (c = 1/10 uniform).
// warp per (i, b-chunk of 8). W row (1280 floats) held in registers,
// reused across the 8 batches. Writes are 128B-coalesced per (b, ou-group).
__global__ __launch_bounds__(256, 4) void k_uhat(const float* __restrict__ inp,
                                                 const float* __restrict__ W) {
    int wg = blockIdx.x * 8 + (threadIdx.x >> 5);   // 0..36863
    int i  = wg >> 5;                               // 0..1151
    int bc = wg & 31;                               // b-chunk
    int l  = threadIdx.x & 31;

    // Load this lane's 5 ou-groups of the W row: ou = g*32 + l, 8 k each.
    const float4* Wp = reinterpret_cast<const float4*>(W + (size_t)i * (OUD * K_DIM));
    float4 w[10];
#pragma unroll
    for (int g = 0; g < 5; g++) {
        int ou = g * 32 + l;
        w[2 * g]     = __ldg(Wp + ou * 2);
        w[2 * g + 1] = __ldg(Wp + ou * 2 + 1);
    }

#pragma unroll
    for (int bb = 0; bb < 8; bb++) {
        int b = bc * 8 + bb;
        const float4* ip = reinterpret_cast<const float4*>(inp + ((size_t)b * IN_CH + i) * K_DIM);
        float4 x0 = __ldg(ip);
        float4 x1 = __ldg(ip + 1);
        float* up = g_uhat + ((size_t)b * IN_CH + i) * OUD;
        float* sp = g_s + b * OUD;
#pragma unroll
        for (int g = 0; g < 5; g++) {
            float o = w[2*g].x * x0.x + w[2*g].y * x0.y + w[2*g].z * x0.z + w[2*g].w * x0.w
                    + w[2*g+1].x * x1.x + w[2*g+1].y * x1.y + w[2*g+1].z * x1.z + w[2*g+1].w * x1.w;
            up[g * 32 + l] = o;
            atomicAdd(&sp[g * 32 + l], 0.1f * o);   // iter-0 c = 1/10
        }
    }
}

// ---------------------------------------------------------------------------
// Squash for iter 0 (g_s -> g_v). 16-lane groups per (b,o).
__global__ void k_squash0() {
    int t = blockIdx.x * 256 + threadIdx.x;         // 40960 threads
    int grp = t >> 4;                                // (b*10+o)
    int b = grp / OUT_CH, o = grp % OUT_CH, l = t & 15;
    float s = g_s[b * OUD + o * OUT_U + l];
    float sq = s * s;
#pragma unroll
    for (int off = 8; off > 0; off >>= 1) sq += __shfl_xor_sync(0xffffffffu, sq, off, 16);
    float v = s * (sq / ((1.0f + sq) * sqrtf(sq + 1e-9f)));
    g_v[b * OUD + o * OUT_U + l] = v;
}

// ---------------------------------------------------------------------------
// Routing-logit update: b[i,o] += (1/256) * sum_{b,u} u_hat[b,i,o,u]*v[b,o,u]
// warp per (i, o-pair): 32 lanes = full 128B line (two o's). No atomics —
// exclusive owner per (i,o). 5760 warps.
__global__ __launch_bounds__(256, 8) void k_delta() {
    int wg = blockIdx.x * 8 + (threadIdx.x >> 5);   // 0..5759
    int op = wg / IN_CH;                            // o-pair 0..4 (outer: L1 v-reuse)
    int i  = wg % IN_CH;
    int l  = threadIdx.x & 31;

    const float* ub = g_uhat + (size_t)i * OUD + op * 32 + l;
    const float* vb = g_v + op * 32 + l;
    float acc = 0.0f;
#pragma unroll 8
    for (int b = 0; b < BATCH; b++)
        acc += __ldg(ub + (size_t)b * UH_BSTRIDE) * __ldg(vb + b * OUD);

    // reduce over u within each 16-lane half (two o's separately)
#pragma unroll
    for (int off = 8; off > 0; off >>= 1) acc += __shfl_xor_sync(0xffffffffu, acc, off, 16);
    if ((l & 15) == 0) {
        int o = op * 2 + (l >> 4);
        g_blog[i * OUT_CH + o] += acc * (1.0f / BATCH);
    }
}

// ---------------------------------------------------------------------------
// Softmax over the 10 output capsules, per input capsule.
__global__ void k_softmax() {
    int i = blockIdx.x * 128 + threadIdx.x;
    if (i >= IN_CH) return;
    float x[OUT_CH], m = -1e30f;
#pragma unroll
    for (int o = 0; o < OUT_CH; o++) { x[o] = g_blog[i * OUT_CH + o]; m = fmaxf(m, x[o]); }
    float sum = 0.0f;
#pragma unroll
    for (int o = 0; o < OUT_CH; o++) { x[o] = __expf(x[o] - m); sum += x[o]; }
    float r = 1.0f / sum;
#pragma unroll
    for (int o = 0; o < OUT_CH; o++) g_c[i * OUT_CH + o] = x[o] * r;
}

// ---------------------------------------------------------------------------
// s = sum_i c[i,o]*u_hat[b,i,o,u], then squash (fused). warp per (b, o-pair):
// 32 lanes = one full 128B line per i. c staged in smem per CTA (all 8 warps
// share the same o-pair). Writes to g_v or d_out.
__global__ __launch_bounds__(256, 4) void k_sv(float* __restrict__ out, int to_out) {
    __shared__ float c_s[IN_CH * 2];                // c for the CTA's two o's
    int op = blockIdx.x / 32;                       // o-pair 0..4
    int bc = blockIdx.x % 32;
    int w  = threadIdx.x >> 5;
    int l  = threadIdx.x & 31;
    int b  = bc * 8 + w;

    for (int idx = threadIdx.x; idx < IN_CH * 2; idx += 256) {
        int i = idx >> 1, oo = idx & 1;
        c_s[idx] = g_c[i * OUT_CH + op * 2 + oo];
    }
    __syncthreads();

    int oo = l >> 4;                                // which o of the pair
    const float* ub = g_uhat + (size_t)b * UH_BSTRIDE + op * 32 + l;
    float acc = 0.0f;
#pragma unroll 8
    for (int i = 0; i < IN_CH; i++)
        acc += __ldg(ub + (size_t)i * OUD) * c_s[i * 2 + oo];

    // squash over u (16-lane halves)
    float sq = acc * acc;
#pragma unroll
    for (int off = 8; off > 0; off >>= 1) sq += __shfl_xor_sync(0xffffffffu, sq, off, 16);
    float v = acc * (sq / ((1.0f + sq) * sqrtf(sq + 1e-9f)));

    float* dst = to_out ? out : g_v;
    dst[b * OUD + op * 32 + l] = v;
}

// ---------------------------------------------------------------------------
extern "C" void kernel_launch(void* const* d_in, const int* in_sizes, int n_in,
                              void* d_out, int out_size) {
    const float* inp = (const float*)d_in[0];
    const float* W   = (const float*)d_in[1];
    if (in_sizes[0] == IN_CH * OUT_CH * OUT_U * K_DIM) {   // defensive: swap if order differs
        W = (const float*)d_in[0];
        inp = (const float*)d_in[1];
    }
    float* out = (float*)d_out;

    k_init<<<(BATCH * OUD + 255) / 256, 256>>>();
    k_uhat<<<IN_CH * 32 / 8, 256>>>(inp, W);               // 4608 CTAs
    k_squash0<<<BATCH * OUD / 256, 256>>>();               // v0
    k_delta<<<IN_CH * 5 / 8, 256>>>();                     // b1   (720 CTAs)
    k_softmax<<<(IN_CH + 127) / 128, 128>>>();             // c1
    k_sv<<<5 * 32, 256>>>(out, 0);                         // v1 -> g_v
    k_delta<<<IN_CH * 5 / 8, 256>>>();                     // b2
    k_softmax<<<(IN_CH + 127) / 128, 128>>>();             // c2
    k_sv<<<5 * 32, 256>>>(out, 1);                         // v2 -> d_out
}

// round 7
// speedup vs baseline: 2.8055x; 2.8055x over previous
#include <cuda_runtime.h>
#include <cuda_bf16.h>
#include <math.h>

// Problem constants
#define BATCH   256
#define IN_CH   1152
#define OUT_CH  10
#define OUT_U   16
#define K_DIM   8
#define NIK     (IN_CH*K_DIM)    // 9216  contraction dim for s-GEMM
#define OUD     (OUT_CH*OUT_U)   // 160
#define KSPLIT  72               // split-K factor for s-GEMM

// Device scratch (allocation-free): ~30 MB total, mostly L2-resident working set
__device__ float g_Wt[NIK * OUD];                 // W transposed: [ik][ou]   (5.9 MB)
__device__ float g_spart[KSPLIT * BATCH * OUD];   // s split-K partials       (11.8 MB)
__device__ float g_mpart[2 * NIK * OUD];          // M = x^T v, 2 batch-splits(11.8 MB)
__device__ float g_v[BATCH * OUD];                // squashed v
__device__ float g_blog[IN_CH * OUT_CH];          // routing logits b
__device__ float g_c[IN_CH * OUT_CH];             // softmax(b) (init 0.1)

// ---------------------------------------------------------------------------
// Packed f32x2 helpers (FFMA2: 2 fp32 FMA per instruction on sm_103a)
__device__ __forceinline__ unsigned long long dupf(float a) {
    unsigned long long r;
    asm("mov.b64 %0, {%1, %1};" : "=l"(r) : "f"(a));
    return r;
}
__device__ __forceinline__ void ffma2(unsigned long long& d,
                                      unsigned long long a, unsigned long long b) {
    asm("fma.rn.f32x2 %0, %1, %2, %0;" : "+l"(d) : "l"(a), "l"(b));
}

// ---------------------------------------------------------------------------
// Per-replay init: zero routing logits, set c to uniform 1/10.
__global__ void k_init() {
    int t = blockIdx.x * 256 + threadIdx.x;
    if (t < IN_CH * OUT_CH) { g_blog[t] = 0.0f; g_c[t] = 0.1f; }
}

// ---------------------------------------------------------------------------
// Wt[(i*8+k)*160 + ou] = W[i*1280 + ou*8 + k]   (k-major -> contraction-major)
__global__ void k_transposeW(const float* __restrict__ W) {
    int idx = blockIdx.x * 256 + threadIdx.x;      // < 1474560
    int ik = idx / 160, ou = idx - ik * 160;
    int i = ik >> 3, k = ik & 7;
    g_Wt[idx] = __ldg(&W[(size_t)i * 1280 + ou * 8 + k]);
}

// ---------------------------------------------------------------------------
// s-GEMM: spart[ks][b][ou] = sum_{ik in chunk} x[b][ik] * c[i,o] * Wt[ik][ou]
// CTA tile 128(b) x 160(ou), K-chunk 128 (KSPLIT=72). 8x10 register tile via
// FFMA2 (8 rows x 5 f32x2-col-pairs). Grid (72, 2), 256 threads.
__global__ __launch_bounds__(256) void k_gemm_s(const float* __restrict__ x) {
    __shared__ float As[16][132];   // [kk][b_local], padded
    __shared__ float Bs[16][164];   // [kk][ou], padded
    int t = threadIdx.x;
    int tx = t & 15, ty = t >> 4;
    int ks = blockIdx.x;
    int b0 = blockIdx.y * 128;
    unsigned long long acc[8][5];
#pragma unroll
    for (int r = 0; r < 8; r++)
#pragma unroll
        for (int j = 0; j < 5; j++) acc[r][j] = 0ULL;

    for (int step = 0; step < 8; step++) {
        int k0 = ks * 128 + step * 16;
        // A: 128 batches x 16 k  (transposed into As[kk][b])
#pragma unroll
        for (int rep = 0; rep < 2; rep++) {
            int idx = t + 256 * rep;
            int r = idx >> 2, q = idx & 3;
            float4 v4 = *reinterpret_cast<const float4*>(
                x + (size_t)(b0 + r) * NIK + k0 + q * 4);
            As[q * 4 + 0][r] = v4.x; As[q * 4 + 1][r] = v4.y;
            As[q * 4 + 2][r] = v4.z; As[q * 4 + 3][r] = v4.w;
        }
        // B: 16 k x 160 ou, scaled by routing coeff c[i,o]
#pragma unroll
        for (int rep = 0; rep < 10; rep++) {
            int e = t + 256 * rep;
            int kk = e / 160, ou = e - kk * 160;
            int ik = k0 + kk;
            float sc = __ldg(&g_c[(ik >> 3) * 10 + (ou >> 4)]);
            Bs[kk][ou] = __ldg(&g_Wt[ik * 160 + ou]) * sc;
        }
        __syncthreads();
#pragma unroll
        for (int kk = 0; kk < 16; kk++) {
            float4 a0 = *reinterpret_cast<const float4*>(&As[kk][ty * 8]);
            float4 a1 = *reinterpret_cast<const float4*>(&As[kk][ty * 8 + 4]);
            unsigned long long ad[8];
            ad[0] = dupf(a0.x); ad[1] = dupf(a0.y); ad[2] = dupf(a0.z); ad[3] = dupf(a0.w);
            ad[4] = dupf(a1.x); ad[5] = dupf(a1.y); ad[6] = dupf(a1.z); ad[7] = dupf(a1.w);
            unsigned long long bv[5];
#pragma unroll
            for (int j = 0; j < 5; j++)
                bv[j] = *reinterpret_cast<const unsigned long long*>(&Bs[kk][tx * 2 + 32 * j]);
#pragma unroll
            for (int r = 0; r < 8; r++)
#pragma unroll
                for (int j = 0; j < 5; j++) ffma2(acc[r][j], ad[r], bv[j]);
        }
        __syncthreads();
    }
    float* outp = g_spart + (size_t)ks * (BATCH * OUD);
#pragma unroll
    for (int r = 0; r < 8; r++) {
        int row = b0 + ty * 8 + r;
#pragma unroll
        for (int j = 0; j < 5; j++) {
            float2 f = *reinterpret_cast<float2*>(&acc[r][j]);
            *reinterpret_cast<float2*>(&outp[row * 160 + tx * 2 + 32 * j]) = f;
        }
    }
}

// ---------------------------------------------------------------------------
// Reduce split-K partials + fused squash. dst==null -> g_v. 40960 threads.
__global__ void k_redsq(float* dst) {
    int t = blockIdx.x * 256 + threadIdx.x;        // b*160 + ou
    float acc = 0.0f;
#pragma unroll
    for (int p = 0; p < KSPLIT; p++) acc += g_spart[(size_t)p * (BATCH * OUD) + t];
    float sq = acc * acc;                          // reduce over u (16-lane groups)
#pragma unroll
    for (int off = 8; off; off >>= 1) sq += __shfl_xor_sync(0xffffffffu, sq, off, 16);
    float v = acc * (sq / ((1.0f + sq) * sqrtf(sq + 1e-9f)));
    float* d = dst ? dst : g_v;
    d[t] = v;
}

// ---------------------------------------------------------------------------
// M-GEMM: mpart[bs][ik][ou] = sum_{b in half} x[b][ik] * v[b][ou]
// CTA tile 128(ik) x 160(ou), contraction = 128 batches. Grid (72, 2).
__global__ __launch_bounds__(256) void k_gemm_M(const float* __restrict__ x) {
    __shared__ float As[16][128];   // [bb][ik_local]
    __shared__ float Bs[16][164];   // [bb][ou]
    int t = threadIdx.x;
    int tx = t & 15, ty = t >> 4;
    int ik0 = blockIdx.x * 128;
    int bs  = blockIdx.y;
    unsigned long long acc[8][5];
#pragma unroll
    for (int r = 0; r < 8; r++)
#pragma unroll
        for (int j = 0; j < 5; j++) acc[r][j] = 0ULL;

    for (int step = 0; step < 8; step++) {
        int b0 = bs * 128 + step * 16;
#pragma unroll
        for (int rep = 0; rep < 2; rep++) {
            int idx = t + 256 * rep;
            int bb = idx >> 5, q = idx & 31;
            float4 v4 = *reinterpret_cast<const float4*>(
                x + (size_t)(b0 + bb) * NIK + ik0 + q * 4);
            *reinterpret_cast<float4*>(&As[bb][q * 4]) = v4;
        }
#pragma unroll
        for (int rep = 0; rep < 10; rep++) {
            int e = t + 256 * rep;
            int bb = e / 160, ou = e - bb * 160;
            Bs[bb][ou] = g_v[(b0 + bb) * 160 + ou];
        }
        __syncthreads();
#pragma unroll
        for (int bb = 0; bb < 16; bb++) {
            float4 a0 = *reinterpret_cast<const float4*>(&As[bb][ty * 8]);
            float4 a1 = *reinterpret_cast<const float4*>(&As[bb][ty * 8 + 4]);
            unsigned long long ad[8];
            ad[0] = dupf(a0.x); ad[1] = dupf(a0.y); ad[2] = dupf(a0.z); ad[3] = dupf(a0.w);
            ad[4] = dupf(a1.x); ad[5] = dupf(a1.y); ad[6] = dupf(a1.z); ad[7] = dupf(a1.w);
            unsigned long long bv[5];
#pragma unroll
            for (int j = 0; j < 5; j++)
                bv[j] = *reinterpret_cast<const unsigned long long*>(&Bs[bb][tx * 2 + 32 * j]);
#pragma unroll
            for (int r = 0; r < 8; r++)
#pragma unroll
                for (int j = 0; j < 5; j++) ffma2(acc[r][j], ad[r], bv[j]);
        }
        __syncthreads();
    }
    float* outp = g_mpart + (size_t)bs * (NIK * OUD);
#pragma unroll
    for (int r = 0; r < 8; r++) {
        int row = ik0 + ty * 8 + r;
#pragma unroll
        for (int j = 0; j < 5; j++) {
            float2 f = *reinterpret_cast<float2*>(&acc[r][j]);
            *reinterpret_cast<float2*>(&outp[row * 160 + tx * 2 + 32 * j]) = f;
        }
    }
}

// ---------------------------------------------------------------------------
// b[i,o] += (1/B) * sum_{k,u} Wt[ik][ou] * (mpart0+mpart1)[ik][ou];
// then fused softmax over o -> g_c. One warp per input capsule i.
__global__ __launch_bounds__(256) void k_bdot() {
    __shared__ float sred[8][10];
    int t = threadIdx.x;
    int w = t >> 5, l = t & 31;
    int i = blockIdx.x * 8 + w;
#pragma unroll
    for (int c5 = 0; c5 < 5; c5++) {
        int ou = c5 * 32 + l;
        float acc = 0.0f;
#pragma unroll
        for (int k = 0; k < 8; k++) {
            int idx = (i * 8 + k) * 160 + ou;
            acc += __ldg(&g_Wt[idx]) *
                   (__ldg(&g_mpart[idx]) + __ldg(&g_mpart[NIK * OUD + idx]));
        }
#pragma unroll
        for (int off = 8; off; off >>= 1) acc += __shfl_xor_sync(0xffffffffu, acc, off, 16);
        if ((l & 15) == 0) sred[w][c5 * 2 + (l >> 4)] = acc;
    }
    __syncwarp();
    float bn = -1e30f;
    if (l < 10) {
        bn = g_blog[i * 10 + l] + sred[w][l] * (1.0f / BATCH);
        g_blog[i * 10 + l] = bn;
    }
    float m = bn;
#pragma unroll
    for (int off = 16; off; off >>= 1) m = fmaxf(m, __shfl_xor_sync(0xffffffffu, m, off));
    float e = (l < 10) ? __expf(bn - m) : 0.0f;
    float s = e;
#pragma unroll
    for (int off = 16; off; off >>= 1) s += __shfl_xor_sync(0xffffffffu, s, off);
    if (l < 10) g_c[i * 10 + l] = e / s;
}

// ---------------------------------------------------------------------------
extern "C" void kernel_launch(void* const* d_in, const int* in_sizes, int n_in,
                              void* d_out, int out_size) {
    const float* inp = (const float*)d_in[0];
    const float* W   = (const float*)d_in[1];
    if (in_sizes[0] == IN_CH * OUT_CH * OUT_U * K_DIM) {   // defensive order check
        W = (const float*)d_in[0];
        inp = (const float*)d_in[1];
    }
    float* out = (float*)d_out;
    dim3 gg(KSPLIT, 2);

    k_init<<<45, 256>>>();
    k_transposeW<<<NIK * OUD / 256, 256>>>(W);
    // epoch 1 (c = 0.1 uniform via g_c init)
    k_gemm_s<<<gg, 256>>>(inp);
    k_redsq<<<BATCH * OUD / 256, 256>>>(nullptr);          // v0
    k_gemm_M<<<gg, 256>>>(inp);
    k_bdot<<<IN_CH / 8, 256>>>();                          // b1, c1
    // epoch 2
    k_gemm_s<<<gg, 256>>>(inp);
    k_redsq<<<BATCH * OUD / 256, 256>>>(nullptr);          // v1
    k_gemm_M<<<gg, 256>>>(inp);
    k_bdot<<<IN_CH / 8, 256>>>();                          // b2, c2
    // epoch 3
    k_gemm_s<<<gg, 256>>>(inp);
    k_redsq<<<BATCH * OUD / 256, 256>>>(out);              // v2 -> output
}

// round 8
// speedup vs baseline: 2.9036x; 1.0350x over previous
#include <cuda_runtime.h>
#include <cuda_bf16.h>
#include <math.h>

// Problem constants
#define BATCH   256
#define IN_CH   1152
#define OUT_CH  10
#define OUT_U   16
#define K_DIM   8
#define NIK     (IN_CH*K_DIM)    // 9216  contraction dim for s-GEMM
#define OUD     (OUT_CH*OUT_U)   // 160
#define KSPLIT  72               // split-K factor for s-GEMM (8 groups x 9)
#define SOUT    (BATCH*OUD)      // 40960

// Device scratch (allocation-free)
__device__ float g_Wt[NIK * OUD];                 // W transposed: [ik][ou]   (5.9 MB)
__device__ float g_spart[KSPLIT * SOUT];          // s split-K partials       (11.8 MB)
__device__ float g_spart2[8 * SOUT];              // stage-1 reduced partials (1.3 MB)
__device__ float g_mpart[2 * NIK * OUD];          // M = x^T v, 2 batch-splits(11.8 MB)
__device__ float g_v[SOUT];                       // squashed v
__device__ float g_blog[IN_CH * OUT_CH];          // routing logits b
__device__ float g_c[IN_CH * OUT_CH];             // softmax(b) (init 0.1)

// ---------------------------------------------------------------------------
// Packed f32x2 helpers (FFMA2: 2 fp32 FMA per instruction on sm_103a)
__device__ __forceinline__ unsigned long long dupf(float a) {
    unsigned long long r;
    asm("mov.b64 %0, {%1, %1};" : "=l"(r) : "f"(a));
    return r;
}
__device__ __forceinline__ void ffma2(unsigned long long& d,
                                      unsigned long long a, unsigned long long b) {
    asm("fma.rn.f32x2 %0, %1, %2, %0;" : "+l"(d) : "l"(a), "l"(b));
}

// ---------------------------------------------------------------------------
// Per-replay init: zero routing logits, set c to uniform 1/10 (softmax of 0).
__global__ void k_init() {
    int t = blockIdx.x * 256 + threadIdx.x;
    if (t < IN_CH * OUT_CH) { g_blog[t] = 0.0f; g_c[t] = 0.1f; }
}

// ---------------------------------------------------------------------------
// Wt[(i*8+k)*160 + ou] = W[i*1280 + ou*8 + k].
// Iterate in W order (coalesced DRAM reads); scattered 4B writes land in L2.
__global__ void k_transposeW(const float* __restrict__ W) {
    int idx = blockIdx.x * 256 + threadIdx.x;      // < 1474560, W-linear
    int i = idx / 1280;
    int r = idx - i * 1280;
    int ou = r >> 3, k = r & 7;
    g_Wt[(i * 8 + k) * 160 + ou] = __ldg(&W[idx]);
}

// ---------------------------------------------------------------------------
// s-GEMM: spart[ks][b][ou] = sum_{ik in chunk} x[b][ik] * c[i,o] * Wt[ik][ou]
// CTA tile 128(b) x 160(ou), K-chunk 128. Register-prefetched double buffer.
__global__ __launch_bounds__(256) void k_gemm_s(const float* __restrict__ x) {
    __shared__ float As[16][132];   // [kk][b_local], padded
    __shared__ float Bs[16][164];   // [kk][ou], padded
    int t = threadIdx.x;
    int tx = t & 15, ty = t >> 4;
    int ks = blockIdx.x;
    int b0 = blockIdx.y * 128;

    float4 pa0, pa1;
    float pw[10], pc[10];
    auto loadT = [&](int K0) {
        int r0 = t >> 2, q0 = t & 3;
        pa0 = *reinterpret_cast<const float4*>(x + (size_t)(b0 + r0) * NIK + K0 + q0 * 4);
        int i1 = t + 256; int r1 = i1 >> 2, q1 = i1 & 3;
        pa1 = *reinterpret_cast<const float4*>(x + (size_t)(b0 + r1) * NIK + K0 + q1 * 4);
#pragma unroll
        for (int rep = 0; rep < 10; rep++) {
            int e = t + 256 * rep;
            int kk = e / 160, ou = e - kk * 160;
            int ik = K0 + kk;
            pw[rep] = __ldg(&g_Wt[ik * 160 + ou]);
            pc[rep] = __ldg(&g_c[(ik >> 3) * 10 + (ou >> 4)]);
        }
    };
    auto storeT = [&]() {
        int r0 = t >> 2, q0 = t & 3;
        As[q0 * 4 + 0][r0] = pa0.x; As[q0 * 4 + 1][r0] = pa0.y;
        As[q0 * 4 + 2][r0] = pa0.z; As[q0 * 4 + 3][r0] = pa0.w;
        int i1 = t + 256; int r1 = i1 >> 2, q1 = i1 & 3;
        As[q1 * 4 + 0][r1] = pa1.x; As[q1 * 4 + 1][r1] = pa1.y;
        As[q1 * 4 + 2][r1] = pa1.z; As[q1 * 4 + 3][r1] = pa1.w;
#pragma unroll
        for (int rep = 0; rep < 10; rep++) {
            int e = t + 256 * rep;
            int kk = e / 160, ou = e - kk * 160;
            Bs[kk][ou] = pw[rep] * pc[rep];
        }
    };

    unsigned long long acc[8][5];
#pragma unroll
    for (int r = 0; r < 8; r++)
#pragma unroll
        for (int j = 0; j < 5; j++) acc[r][j] = 0ULL;

    loadT(ks * 128);
    for (int step = 0; step < 8; step++) {
        storeT();
        __syncthreads();
        if (step < 7) loadT(ks * 128 + (step + 1) * 16);   // overlap with compute
#pragma unroll
        for (int kk = 0; kk < 16; kk++) {
            float4 a0 = *reinterpret_cast<const float4*>(&As[kk][ty * 8]);
            float4 a1 = *reinterpret_cast<const float4*>(&As[kk][ty * 8 + 4]);
            unsigned long long ad[8];
            ad[0] = dupf(a0.x); ad[1] = dupf(a0.y); ad[2] = dupf(a0.z); ad[3] = dupf(a0.w);
            ad[4] = dupf(a1.x); ad[5] = dupf(a1.y); ad[6] = dupf(a1.z); ad[7] = dupf(a1.w);
            unsigned long long bv[5];
#pragma unroll
            for (int j = 0; j < 5; j++)
                bv[j] = *reinterpret_cast<const unsigned long long*>(&Bs[kk][tx * 2 + 32 * j]);
#pragma unroll
            for (int r = 0; r < 8; r++)
#pragma unroll
                for (int j = 0; j < 5; j++) ffma2(acc[r][j], ad[r], bv[j]);
        }
        __syncthreads();
    }
    float* outp = g_spart + (size_t)ks * SOUT;
#pragma unroll
    for (int r = 0; r < 8; r++) {
        int row = b0 + ty * 8 + r;
#pragma unroll
        for (int j = 0; j < 5; j++) {
            float2 f = *reinterpret_cast<float2*>(&acc[r][j]);
            *reinterpret_cast<float2*>(&outp[row * 160 + tx * 2 + 32 * j]) = f;
        }
    }
}

// ---------------------------------------------------------------------------
// Split-K reduce stage 1: 72 -> 8 partials. grid (160, 8), 327K threads.
__global__ void k_red1() {
    int e = blockIdx.x * 256 + threadIdx.x;
    int g = blockIdx.y;
    float a = 0.0f;
#pragma unroll
    for (int p = 0; p < 9; p++) a += g_spart[(size_t)(g * 9 + p) * SOUT + e];
    g_spart2[g * SOUT + e] = a;
}

// Split-K reduce stage 2: sum 8 + fused squash. dst==null -> g_v.
__global__ void k_red2(float* dst) {
    int t = blockIdx.x * 256 + threadIdx.x;        // b*160 + ou
    float acc = 0.0f;
#pragma unroll
    for (int p = 0; p < 8; p++) acc += g_spart2[p * SOUT + t];
    float sq = acc * acc;                          // reduce over u (16-lane groups)
#pragma unroll
    for (int off = 8; off; off >>= 1) sq += __shfl_xor_sync(0xffffffffu, sq, off, 16);
    float v = acc * (sq / ((1.0f + sq) * sqrtf(sq + 1e-9f)));
    float* d = dst ? dst : g_v;
    d[t] = v;
}

// ---------------------------------------------------------------------------
// M-GEMM: mpart[bs][ik][ou] = sum_{b in half} x[b][ik] * v[b][ou]
// CTA tile 128(ik) x 160(ou), contraction = 128 batches. Prefetched.
__global__ __launch_bounds__(256) void k_gemm_M(const float* __restrict__ x) {
    __shared__ float As[16][128];   // [bb][ik_local]
    __shared__ float Bs[16][164];   // [bb][ou]
    int t = threadIdx.x;
    int tx = t & 15, ty = t >> 4;
    int ik0 = blockIdx.x * 128;
    int bs  = blockIdx.y;

    float4 pa0, pa1;
    float pv[10];
    auto loadT = [&](int B0) {
        int b0 = t >> 5, q0 = t & 31;
        pa0 = *reinterpret_cast<const float4*>(x + (size_t)(B0 + b0) * NIK + ik0 + q0 * 4);
        int i1 = t + 256; int b1 = i1 >> 5, q1 = i1 & 31;
        pa1 = *reinterpret_cast<const float4*>(x + (size_t)(B0 + b1) * NIK + ik0 + q1 * 4);
#pragma unroll
        for (int rep = 0; rep < 10; rep++) {
            int e = t + 256 * rep;
            int bb = e / 160, ou = e - bb * 160;
            pv[rep] = __ldg(&g_v[(B0 + bb) * 160 + ou]);
        }
    };
    auto storeT = [&]() {
        int b0 = t >> 5, q0 = t & 31;
        *reinterpret_cast<float4*>(&As[b0][q0 * 4]) = pa0;
        int i1 = t + 256; int b1 = i1 >> 5, q1 = i1 & 31;
        *reinterpret_cast<float4*>(&As[b1][q1 * 4]) = pa1;
#pragma unroll
        for (int rep = 0; rep < 10; rep++) {
            int e = t + 256 * rep;
            int bb = e / 160, ou = e - bb * 160;
            Bs[bb][ou] = pv[rep];
        }
    };

    unsigned long long acc[8][5];
#pragma unroll
    for (int r = 0; r < 8; r++)
#pragma unroll
        for (int j = 0; j < 5; j++) acc[r][j] = 0ULL;

    loadT(bs * 128);
    for (int step = 0; step < 8; step++) {
        storeT();
        __syncthreads();
        if (step < 7) loadT(bs * 128 + (step + 1) * 16);
#pragma unroll
        for (int bb = 0; bb < 16; bb++) {
            float4 a0 = *reinterpret_cast<const float4*>(&As[bb][ty * 8]);
            float4 a1 = *reinterpret_cast<const float4*>(&As[bb][ty * 8 + 4]);
            unsigned long long ad[8];
            ad[0] = dupf(a0.x); ad[1] = dupf(a0.y); ad[2] = dupf(a0.z); ad[3] = dupf(a0.w);
            ad[4] = dupf(a1.x); ad[5] = dupf(a1.y); ad[6] = dupf(a1.z); ad[7] = dupf(a1.w);
            unsigned long long bv[5];
#pragma unroll
            for (int j = 0; j < 5; j++)
                bv[j] = *reinterpret_cast<const unsigned long long*>(&Bs[bb][tx * 2 + 32 * j]);
#pragma unroll
            for (int r = 0; r < 8; r++)
#pragma unroll
                for (int j = 0; j < 5; j++) ffma2(acc[r][j], ad[r], bv[j]);
        }
        __syncthreads();
    }
    float* outp = g_mpart + (size_t)bs * (NIK * OUD);
#pragma unroll
    for (int r = 0; r < 8; r++) {
        int row = ik0 + ty * 8 + r;
#pragma unroll
        for (int j = 0; j < 5; j++) {
            float2 f = *reinterpret_cast<float2*>(&acc[r][j]);
            *reinterpret_cast<float2*>(&outp[row * 160 + tx * 2 + 32 * j]) = f;
        }
    }
}

// ---------------------------------------------------------------------------
// b[i,o] += (1/B) * sum_{k,u} Wt[ik][ou]*(mpart0+mpart1)[ik][ou], fused
// softmax over o -> g_c. Block per input capsule i, thread per ou (160 thr).
__global__ __launch_bounds__(160) void k_bdot() {
    __shared__ float so[10];
    int i = blockIdx.x;
    int t = threadIdx.x;                            // = ou
    float acc = 0.0f;
#pragma unroll
    for (int k = 0; k < 8; k++) {
        int idx = (i * 8 + k) * 160 + t;
        acc += __ldg(&g_Wt[idx]) *
               (__ldg(&g_mpart[idx]) + __ldg(&g_mpart[NIK * OUD + idx]));
    }
#pragma unroll
    for (int off = 8; off; off >>= 1) acc += __shfl_xor_sync(0xffffffffu, acc, off, 16);
    if ((t & 15) == 0) so[t >> 4] = acc;
    __syncthreads();
    float bn = -1e30f;
    if (t < 10) {
        bn = g_blog[i * 10 + t] + so[t] * (1.0f / BATCH);
        g_blog[i * 10 + t] = bn;
    }
    // softmax within lanes 0..15 of warp 0 (lanes 10..15 hold -inf / 0)
    float m = bn;
#pragma unroll
    for (int off = 8; off; off >>= 1) m = fmaxf(m, __shfl_xor_sync(0xffffffffu, m, off, 16));
    float e = (t < 10) ? __expf(bn - m) : 0.0f;
    float s = e;
#pragma unroll
    for (int off = 8; off; off >>= 1) s += __shfl_xor_sync(0xffffffffu, s, off, 16);
    if (t < 10) g_c[i * 10 + t] = e / s;
}

// ---------------------------------------------------------------------------
extern "C" void kernel_launch(void* const* d_in, const int* in_sizes, int n_in,
                              void* d_out, int out_size) {
    const float* inp = (const float*)d_in[0];
    const float* W   = (const float*)d_in[1];
    if (in_sizes[0] == IN_CH * OUT_CH * OUT_U * K_DIM) {   // defensive order check
        W = (const float*)d_in[0];
        inp = (const float*)d_in[1];
    }
    float* out = (float*)d_out;
    dim3 gg(KSPLIT, 2);
    dim3 gr1(160, 8);

    k_init<<<45, 256>>>();
    k_transposeW<<<NIK * OUD / 256, 256>>>(W);
    // epoch 1 (c = 0.1 uniform)
    k_gemm_s<<<gg, 256>>>(inp);
    k_red1<<<gr1, 256>>>();
    k_red2<<<160, 256>>>(nullptr);                         // v0
    k_gemm_M<<<gg, 256>>>(inp);
    k_bdot<<<IN_CH, 160>>>();                              // b1, c1
    // epoch 2
    k_gemm_s<<<gg, 256>>>(inp);
    k_red1<<<gr1, 256>>>();
    k_red2<<<160, 256>>>(nullptr);                         // v1
    k_gemm_M<<<gg, 256>>>(inp);
    k_bdot<<<IN_CH, 160>>>();                              // b2, c2
    // epoch 3
    k_gemm_s<<<gg, 256>>>(inp);
    k_red1<<<gr1, 256>>>();
    k_red2<<<160, 256>>>(out);                             // v2 -> output
}

// round 10
// speedup vs baseline: 3.1343x; 1.0794x over previous
#include <cuda_runtime.h>
#include <cuda_bf16.h>
#include <math.h>
#include <cstdint>

// ---------------------------------------------------------------------------
// Problem constants
#define BATCH   256
#define IN_CH   1152
#define OUT_CH  10
#define OUT_U   16
#define NIK     9216             // IN_CH*8, contraction dim for s-GEMM
#define OUD     160              // OUT_CH*OUT_U
#define KSPLIT  72
#define SOUT    40960            // BATCH*OUD
#define MO      (NIK*OUD)        // 1474560

// ---------------------------------------------------------------------------
// Device scratch (allocation-free)
__device__ __align__(16) __nv_bfloat16 g_xh[BATCH * NIK], g_xl[BATCH * NIK];   // x split  [b][ik]
__device__ __align__(16) __nv_bfloat16 g_xTh[NIK * BATCH], g_xTl[NIK * BATCH]; // x^T split[ik][b]
__device__ __align__(16) __nv_bfloat16 g_Bch[MO], g_Bcl[MO];                   // (c∘W) split [ou][ik]
__device__ __align__(16) __nv_bfloat16 g_vTh[OUD * BATCH], g_vTl[OUD * BATCH]; // v^T split [ou][b]
__device__ __align__(16) float g_Wt[MO];                 // W transposed [ik][ou] (for bdot)
__device__ __align__(16) float g_spart[KSPLIT * SOUT];   // s split-K partials
__device__ __align__(16) float g_spart2[8 * SOUT];       // stage-1 reduced
__device__ __align__(16) float g_mpart[2 * MO];          // M = x^T v, 2 halves
__device__ float g_blog[IN_CH * OUT_CH];
__device__ float g_c[IN_CH * OUT_CH];

// ---------------------------------------------------------------------------
// Warp-level bf16 MMA (baseline PTX, valid on bare sm_103 target)
#define MMA_BF16(c, A0, A1, A2, A3, B0, B1)                                   \
    asm volatile("mma.sync.aligned.m16n8k16.row.col.f32.bf16.bf16.f32 "       \
                 "{%0,%1,%2,%3}, {%4,%5,%6,%7}, {%8,%9}, {%0,%1,%2,%3};"      \
                 : "+f"((c)[0]), "+f"((c)[1]), "+f"((c)[2]), "+f"((c)[3])     \
                 : "r"(A0), "r"(A1), "r"(A2), "r"(A3), "r"(B0), "r"(B1))

// SMEM layout (u32 words, row stride 68 words = 272B; 68 mod 32 = 4 ->
// fragment loads bank = (4r + c) mod 32, perfectly conflict-free)
#define ROWW 68
#define SM_AH 0
#define SM_AL 34816                    // 128*68*4
#define SM_BH 69632                    // 2*34816
#define SM_BL 113152                   // +160*68*4 = 43520
#define SM_TOTAL 156672                // +43520

// ---------------------------------------------------------------------------
__global__ void k_init() {
    int t = blockIdx.x * 256 + threadIdx.x;
    if (t < IN_CH * OUT_CH) { g_blog[t] = 0.0f; g_c[t] = 0.1f; }
}

// x -> bf16 hi/lo split, [b][ik] layout (coalesced)
__global__ void k_split_x(const float* __restrict__ x) {
    int idx = blockIdx.x * 256 + threadIdx.x;     // < BATCH*NIK
    float f = x[idx];
    __nv_bfloat16 h = __float2bfloat16(f);
    g_xh[idx] = h;
    g_xl[idx] = __float2bfloat16(f - __bfloat162float(h));
}

// x -> x^T bf16 hi/lo split via 32x32 smem tiles
__global__ void k_transpose_x(const float* __restrict__ x) {
    __shared__ float s[32][33];
    int ik0 = blockIdx.x * 32, b0 = blockIdx.y * 32;
    int t = threadIdx.x, tr = t >> 5, tc = t & 31;
#pragma unroll
    for (int j = 0; j < 4; j++)
        s[tr + 8 * j][tc] = x[(size_t)(b0 + tr + 8 * j) * NIK + ik0 + tc];
    __syncthreads();
#pragma unroll
    for (int j = 0; j < 4; j++) {
        int ikl = tr + 8 * j;
        float f = s[tc][ikl];
        __nv_bfloat16 h = __float2bfloat16(f);
        size_t o = (size_t)(ik0 + ikl) * BATCH + b0 + tc;
        g_xTh[o] = h;
        g_xTl[o] = __float2bfloat16(f - __bfloat162float(h));
    }
}

// Wt[(i*8+k)*160+ou] = W[i*1280+ou*8+k]   (bdot operand)
__global__ void k_transposeW(const float* __restrict__ W) {
    int idx = blockIdx.x * 256 + threadIdx.x;     // W-linear
    int i = idx / 1280;
    int r = idx - i * 1280;
    g_Wt[(i * 8 + (r & 7)) * 160 + (r >> 3)] = __ldg(&W[idx]);
}

// Bc[ou][ik] = W[i][ou][k] * c[i,o], bf16 hi/lo. Output-coalesced.
__global__ void k_makeB(const float* __restrict__ W) {
    int idx = blockIdx.x * 256 + threadIdx.x;     // < MO, = ou*NIK+ik
    int ou = idx / NIK, ik = idx - ou * NIK;
    int i = ik >> 3, k = ik & 7;
    float f = __ldg(&W[(size_t)i * 1280 + ou * 8 + k]) * __ldg(&g_c[i * 10 + (ou >> 4)]);
    __nv_bfloat16 h = __float2bfloat16(f);
    g_Bch[idx] = h;
    g_Bcl[idx] = __float2bfloat16(f - __bfloat162float(h));
}

// ---------------------------------------------------------------------------
// Warp-MMA GEMM: D[128 x 160] = A[128 x 128k] · B[160 x 128k]^T, bf16x3.
// mode 0 (s-GEMM):  A=x[b][ik],  B=Bc[ou][ik],  out=spart[ks]   grid (72,2)
// mode 1 (M-GEMM):  A=xT[ik][b], B=vT[ou][b],   out=mpart[bs]   grid (72,2)
__global__ __launch_bounds__(256) void k_mma(int mode) {
    extern __shared__ uint32_t sm4[];
    uint32_t* aS_h = sm4 + SM_AH / 4;
    uint32_t* aS_l = sm4 + SM_AL / 4;
    uint32_t* bS_h = sm4 + SM_BH / 4;
    uint32_t* bS_l = sm4 + SM_BL / 4;
    int t = threadIdx.x;

    const __nv_bfloat16 *Ah_g, *Al_g, *Bh_g, *Bl_g;
    int astr, bstr, arow0, k0;
    float* outp;
    if (mode == 0) {
        Ah_g = g_xh;  Al_g = g_xl;  astr = NIK;   arow0 = blockIdx.y * 128;
        Bh_g = g_Bch; Bl_g = g_Bcl; bstr = NIK;   k0 = blockIdx.x * 128;
        outp = g_spart + (size_t)blockIdx.x * SOUT;
    } else {
        Ah_g = g_xTh; Al_g = g_xTl; astr = BATCH; arow0 = blockIdx.x * 128;
        Bh_g = g_vTh; Bl_g = g_vTl; bstr = BATCH; k0 = blockIdx.y * 128;
        outp = g_mpart + (size_t)blockIdx.y * MO;
    }

    // Stage A (128 x 128 bf16, hi+lo)
#pragma unroll
    for (int it = 0; it < 8; it++) {
        int idx = t + 256 * it, r = idx >> 4, seg = idx & 15;
        size_t g = (size_t)(arow0 + r) * astr + k0 + seg * 8;
        *reinterpret_cast<uint4*>(aS_h + r * ROWW + seg * 4) =
            *reinterpret_cast<const uint4*>(Ah_g + g);
        *reinterpret_cast<uint4*>(aS_l + r * ROWW + seg * 4) =
            *reinterpret_cast<const uint4*>(Al_g + g);
    }
    // Stage B (160 x 128 bf16, hi+lo)
#pragma unroll
    for (int it = 0; it < 10; it++) {
        int idx = t + 256 * it, r = idx >> 4, seg = idx & 15;
        size_t g = (size_t)r * bstr + k0 + seg * 8;
        *reinterpret_cast<uint4*>(bS_h + r * ROWW + seg * 4) =
            *reinterpret_cast<const uint4*>(Bh_g + g);
        *reinterpret_cast<uint4*>(bS_l + r * ROWW + seg * 4) =
            *reinterpret_cast<const uint4*>(Bl_g + g);
    }
    __syncthreads();

    int wid = t >> 5, lane = t & 31;
    int wm = wid & 3, wn = wid >> 2;               // 4 m-warps x 2 n-warps
    int qrow = lane >> 2, qcol = lane & 3;

    float acc[2][10][4];
#pragma unroll
    for (int mt = 0; mt < 2; mt++)
#pragma unroll
        for (int nt = 0; nt < 10; nt++)
#pragma unroll
            for (int j = 0; j < 4; j++) acc[mt][nt][j] = 0.0f;

#pragma unroll
    for (int ks = 0; ks < 8; ks++) {
        uint32_t bh[10][2], bl[10][2];
#pragma unroll
        for (int nt = 0; nt < 10; nt++) {
            int w = (wn * 80 + nt * 8 + qrow) * ROWW + ks * 8 + qcol;
            bh[nt][0] = bS_h[w]; bh[nt][1] = bS_h[w + 4];
            bl[nt][0] = bS_l[w]; bl[nt][1] = bS_l[w + 4];
        }
#pragma unroll
        for (int mt = 0; mt < 2; mt++) {
            int w = (wm * 32 + mt * 16 + qrow) * ROWW + ks * 8 + qcol;
            uint32_t ah0 = aS_h[w], ah1 = aS_h[w + 8 * ROWW];
            uint32_t ah2 = aS_h[w + 4], ah3 = aS_h[w + 8 * ROWW + 4];
            uint32_t al0 = aS_l[w], al1 = aS_l[w + 8 * ROWW];
            uint32_t al2 = aS_l[w + 4], al3 = aS_l[w + 8 * ROWW + 4];
#pragma unroll
            for (int nt = 0; nt < 10; nt++) {
                MMA_BF16(acc[mt][nt], ah0, ah1, ah2, ah3, bh[nt][0], bh[nt][1]); // hi*hi
                MMA_BF16(acc[mt][nt], ah0, ah1, ah2, ah3, bl[nt][0], bl[nt][1]); // hi*lo
                MMA_BF16(acc[mt][nt], al0, al1, al2, al3, bh[nt][0], bh[nt][1]); // lo*hi
            }
        }
    }

    // Epilogue: c-frag rows = A rows, cols = B rows (ou / same layout both modes)
#pragma unroll
    for (int mt = 0; mt < 2; mt++) {
        int row = arow0 + wm * 32 + mt * 16 + qrow;
#pragma unroll
        for (int nt = 0; nt < 10; nt++) {
            int col = wn * 80 + nt * 8 + qcol * 2;
            *reinterpret_cast<float2*>(outp + (size_t)row * 160 + col) =
                make_float2(acc[mt][nt][0], acc[mt][nt][1]);
            *reinterpret_cast<float2*>(outp + (size_t)(row + 8) * 160 + col) =
                make_float2(acc[mt][nt][2], acc[mt][nt][3]);
        }
    }
}

// ---------------------------------------------------------------------------
// Split-K reduce stage 1 (float4): 72 -> 8 partials. grid (40,8) x 256.
__global__ void k_red1() {
    int e4 = blockIdx.x * 256 + threadIdx.x;       // < 10240
    int g = blockIdx.y;
    const float4* sp = reinterpret_cast<const float4*>(g_spart);
    float4 a = make_float4(0.f, 0.f, 0.f, 0.f);
#pragma unroll
    for (int p = 0; p < 9; p++) {
        float4 v = sp[(size_t)(g * 9 + p) * 10240 + e4];
        a.x += v.x; a.y += v.y; a.z += v.z; a.w += v.w;
    }
    reinterpret_cast<float4*>(g_spart2)[(size_t)g * 10240 + e4] = a;
}

// Stage 2 + squash (+ v^T bf16 split for the next M-GEMM). grid 40 x 256.
__global__ void k_red2(float* dst, int writeVT) {
    int t4 = blockIdx.x * 256 + threadIdx.x;       // < 10240
    const float4* sp = reinterpret_cast<const float4*>(g_spart2);
    float4 a = make_float4(0.f, 0.f, 0.f, 0.f);
#pragma unroll
    for (int p = 0; p < 8; p++) {
        float4 v = sp[(size_t)p * 10240 + t4];
        a.x += v.x; a.y += v.y; a.z += v.z; a.w += v.w;
    }
    float sq = a.x * a.x + a.y * a.y + a.z * a.z + a.w * a.w;
    sq += __shfl_xor_sync(0xffffffffu, sq, 1);     // 4 lanes = 16 u's
    sq += __shfl_xor_sync(0xffffffffu, sq, 2);
    float m = sq / ((1.0f + sq) * sqrtf(sq + 1e-9f));
    float4 v = make_float4(a.x * m, a.y * m, a.z * m, a.w * m);
    if (writeVT) {
        int elem0 = t4 * 4;
        int b = elem0 / 160, ou0 = elem0 - b * 160;
        float vv[4] = {v.x, v.y, v.z, v.w};
#pragma unroll
        for (int j = 0; j < 4; j++) {
            __nv_bfloat16 h = __float2bfloat16(vv[j]);
            size_t o = (size_t)(ou0 + j) * BATCH + b;
            g_vTh[o] = h;
            g_vTl[o] = __float2bfloat16(vv[j] - __bfloat162float(h));
        }
    } else {
        reinterpret_cast<float4*>(dst)[t4] = v;
    }
}

// ---------------------------------------------------------------------------
// b[i,o] += (1/B) * sum_{k,u} Wt[ik][ou]*(mpart0+mpart1)[ik][ou]; fused softmax.
__global__ __launch_bounds__(160) void k_bdot() {
    __shared__ float so[10];
    int i = blockIdx.x;
    int t = threadIdx.x;                            // = ou
    float acc = 0.0f;
#pragma unroll
    for (int k = 0; k < 8; k++) {
        int idx = (i * 8 + k) * 160 + t;
        acc += __ldg(&g_Wt[idx]) * (__ldg(&g_mpart[idx]) + __ldg(&g_mpart[MO + idx]));
    }
#pragma unroll
    for (int off = 8; off; off >>= 1) acc += __shfl_xor_sync(0xffffffffu, acc, off, 16);
    if ((t & 15) == 0) so[t >> 4] = acc;
    __syncthreads();
    float bn = -1e30f;
    if (t < 10) {
        bn = g_blog[i * 10 + t] + so[t] * (1.0f / BATCH);
        g_blog[i * 10 + t] = bn;
    }
    float m = bn;
#pragma unroll
    for (int off = 8; off; off >>= 1) m = fmaxf(m, __shfl_xor_sync(0xffffffffu, m, off, 16));
    float e = (t < 10) ? __expf(bn - m) : 0.0f;
    float s = e;
#pragma unroll
    for (int off = 8; off; off >>= 1) s += __shfl_xor_sync(0xffffffffu, s, off, 16);
    if (t < 10) g_c[i * 10 + t] = e / s;
}

// ---------------------------------------------------------------------------
extern "C" void kernel_launch(void* const* d_in, const int* in_sizes, int n_in,
                              void* d_out, int out_size) {
    const float* inp = (const float*)d_in[0];
    const float* W   = (const float*)d_in[1];
    if (in_sizes[0] == IN_CH * OUT_CH * OUT_U * 8) {       // defensive order check
        W = (const float*)d_in[0];
        inp = (const float*)d_in[1];
    }
    float* out = (float*)d_out;

    // Opt-in to >48KB dynamic smem (host attribute, capture-safe, idempotent).
    cudaFuncSetAttribute(k_mma, cudaFuncAttributeMaxDynamicSharedMemorySize, SM_TOTAL);

    dim3 gg(KSPLIT, 2), gt(NIK / 32, BATCH / 32), gr1(40, 8);

    k_init<<<45, 256>>>();
    k_split_x<<<BATCH * NIK / 256, 256>>>(inp);
    k_transpose_x<<<gt, 256>>>(inp);
    k_transposeW<<<MO / 256, 256>>>(W);
    // epoch 1 (c = 0.1 uniform)
    k_makeB<<<MO / 256, 256>>>(W);
    k_mma<<<gg, 256, SM_TOTAL>>>(0);
    k_red1<<<gr1, 256>>>();
    k_red2<<<40, 256>>>(nullptr, 1);                       // v0 -> vT
    k_mma<<<gg, 256, SM_TOTAL>>>(1);
    k_bdot<<<IN_CH, 160>>>();                              // b1, c1
    // epoch 2
    k_makeB<<<MO / 256, 256>>>(W);
    k_mma<<<gg, 256, SM_TOTAL>>>(0);
    k_red1<<<gr1, 256>>>();
    k_red2<<<40, 256>>>(nullptr, 1);                       // v1 -> vT
    k_mma<<<gg, 256, SM_TOTAL>>>(1);
    k_bdot<<<IN_CH, 160>>>();                              // b2, c2
    // epoch 3
    k_makeB<<<MO / 256, 256>>>(W);
    k_mma<<<gg, 256, SM_TOTAL>>>(0);
    k_red1<<<gr1, 256>>>();
    k_red2<<<40, 256>>>(out, 0);                           // v2 -> output
}

// round 11
// speedup vs baseline: 3.8469x; 1.2274x over previous
#include <cuda_runtime.h>
#include <cuda_bf16.h>
#include <math.h>
#include <cstdint>

// ---------------------------------------------------------------------------
// Problem constants
#define BATCH   256
#define IN_CH   1152
#define OUT_CH  10
#define OUT_U   16
#define NIK     9216             // IN_CH*8, contraction dim for s-GEMM
#define OUD     160              // OUT_CH*OUT_U
#define KSPLIT  72
#define SOUT    40960            // BATCH*OUD
#define MO      (NIK*OUD)        // 1474560

// ---------------------------------------------------------------------------
// Device scratch (allocation-free)
__device__ __align__(16) __nv_bfloat16 g_xh[BATCH * NIK], g_xl[BATCH * NIK];   // x split  [b][ik]
__device__ __align__(16) __nv_bfloat16 g_xTh[NIK * BATCH], g_xTl[NIK * BATCH]; // x^T split[ik][b]
__device__ __align__(16) __nv_bfloat16 g_Wsh[MO], g_Wsl[MO];                   // W split [ou][ik]
__device__ __align__(16) __nv_bfloat16 g_vTh[OUD * BATCH], g_vTl[OUD * BATCH]; // v^T split [ou][b]
__device__ __align__(16) float g_spart[KSPLIT * SOUT];   // s split-K partials
__device__ __align__(16) float g_spart2[8 * SOUT];       // stage-1 reduced
__device__ __align__(16) float g_mpart[2 * MO];          // M = x^T v, 2 halves
__device__ float g_blog[IN_CH * OUT_CH];
__device__ float g_c[IN_CH * OUT_CH];

// ---------------------------------------------------------------------------
// Warp-level bf16 MMA (baseline PTX, valid on bare sm_103 target)
#define MMA_BF16(c, A0, A1, A2, A3, B0, B1)                                   \
    asm volatile("mma.sync.aligned.m16n8k16.row.col.f32.bf16.bf16.f32 "       \
                 "{%0,%1,%2,%3}, {%4,%5,%6,%7}, {%8,%9}, {%0,%1,%2,%3};"      \
                 : "+f"((c)[0]), "+f"((c)[1]), "+f"((c)[2]), "+f"((c)[3])     \
                 : "r"(A0), "r"(A1), "r"(A2), "r"(A3), "r"(B0), "r"(B1))

// SMEM layout (u32 words, row stride 68 words = 272B; 68 mod 32 = 4 ->
// fragment loads bank = (4r + c) mod 32, conflict-free)
#define ROWW 68
#define SM_AH 0
#define SM_AL 34816                    // 128*68*4
#define SM_BH 69632
#define SM_BL 113152                   // +160*68*4 = 43520
#define SM_TOTAL 156672

// ---------------------------------------------------------------------------
__global__ void k_init() {
    int t = blockIdx.x * 256 + threadIdx.x;
    if (t < IN_CH * OUT_CH) { g_blog[t] = 0.0f; g_c[t] = 0.1f; }
}

// One-time W -> bf16 hi/lo split in [ou][ik] layout (output-coalesced).
__global__ void k_splitW(const float* __restrict__ W) {
    int idx = blockIdx.x * 256 + threadIdx.x;     // < MO, = ou*NIK+ik
    int ou = idx / NIK, ik = idx - ou * NIK;
    float f = __ldg(&W[(size_t)(ik >> 3) * 1280 + ou * 8 + (ik & 7)]);
    __nv_bfloat16 h = __float2bfloat16(f);
    g_Wsh[idx] = h;
    g_Wsl[idx] = __float2bfloat16(f - __bfloat162float(h));
}

// x -> bf16 hi/lo split in BOTH [b][ik] and [ik][b] layouts (single x read).
__global__ void k_split_x(const float* __restrict__ x) {
    __shared__ float s[32][33];
    int ik0 = blockIdx.x * 32, b0 = blockIdx.y * 32;
    int t = threadIdx.x, tr = t >> 5, tc = t & 31;
#pragma unroll
    for (int j = 0; j < 4; j++)
        s[tr + 8 * j][tc] = x[(size_t)(b0 + tr + 8 * j) * NIK + ik0 + tc];
    __syncthreads();
#pragma unroll
    for (int j = 0; j < 4; j++) {
        int r = tr + 8 * j;
        float f = s[r][tc];                        // direct: row=b, col=ik
        __nv_bfloat16 h = __float2bfloat16(f);
        size_t o = (size_t)(b0 + r) * NIK + ik0 + tc;
        g_xh[o] = h;
        g_xl[o] = __float2bfloat16(f - __bfloat162float(h));
        float ft = s[tc][r];                       // transposed: row=ik, col=b
        __nv_bfloat16 h2 = __float2bfloat16(ft);
        size_t o2 = (size_t)(ik0 + r) * BATCH + b0 + tc;
        g_xTh[o2] = h2;
        g_xTl[o2] = __float2bfloat16(ft - __bfloat162float(h2));
    }
}

// ---------------------------------------------------------------------------
// Warp-MMA GEMM: D[128 x 160] = A[128 x 128k] · B[160 x 128k]^T, bf16x3.
// mode 0 (s-GEMM): A=x[b][ik], B=(c∘W)[ou][ik] built on the fly from Wsh/Wsl.
// mode 1 (M-GEMM): A=xT[ik][b], B=vT[ou][b].
__global__ __launch_bounds__(256) void k_mma(int mode) {
    extern __shared__ uint32_t sm4[];
    uint32_t* aS_h = sm4 + SM_AH / 4;
    uint32_t* aS_l = sm4 + SM_AL / 4;
    uint32_t* bS_h = sm4 + SM_BH / 4;
    uint32_t* bS_l = sm4 + SM_BL / 4;
    int t = threadIdx.x;

    const __nv_bfloat16 *Ah_g, *Al_g;
    int astr, arow0, k0;
    float* outp;
    if (mode == 0) {
        Ah_g = g_xh;  Al_g = g_xl;  astr = NIK;   arow0 = blockIdx.y * 128;
        k0 = blockIdx.x * 128;
        outp = g_spart + (size_t)blockIdx.x * SOUT;
    } else {
        Ah_g = g_xTh; Al_g = g_xTl; astr = BATCH; arow0 = blockIdx.x * 128;
        k0 = blockIdx.y * 128;
        outp = g_mpart + (size_t)blockIdx.y * MO;
    }

    // Stage A (128 x 128 bf16, hi+lo)
#pragma unroll
    for (int it = 0; it < 8; it++) {
        int idx = t + 256 * it, r = idx >> 4, seg = idx & 15;
        size_t g = (size_t)(arow0 + r) * astr + k0 + seg * 8;
        *reinterpret_cast<uint4*>(aS_h + r * ROWW + seg * 4) =
            *reinterpret_cast<const uint4*>(Ah_g + g);
        *reinterpret_cast<uint4*>(aS_l + r * ROWW + seg * 4) =
            *reinterpret_cast<const uint4*>(Al_g + g);
    }
    // Stage B (160 x 128 bf16, hi+lo)
    if (mode == 0) {
        // Fused c-scaling: B = c[i,o] * (Wh + Wl), re-split to hi/lo bf16.
        // seg*8 spans exactly one input capsule i (k=0..7), so one c per uint4.
#pragma unroll
        for (int it = 0; it < 10; it++) {
            int idx = t + 256 * it, r = idx >> 4, seg = idx & 15;
            size_t g = (size_t)r * NIK + k0 + seg * 8;
            float c = __ldg(&g_c[((k0 + seg * 8) >> 3) * 10 + (r >> 4)]);
            uint4 h4 = *reinterpret_cast<const uint4*>(g_Wsh + g);
            uint4 l4 = *reinterpret_cast<const uint4*>(g_Wsl + g);
            uint32_t hw[4] = {h4.x, h4.y, h4.z, h4.w};
            uint32_t lw[4] = {l4.x, l4.y, l4.z, l4.w};
            uint32_t oh[4], ol[4];
#pragma unroll
            for (int q = 0; q < 4; q++) {
                __nv_bfloat162 hb = *reinterpret_cast<__nv_bfloat162*>(&hw[q]);
                __nv_bfloat162 lb = *reinterpret_cast<__nv_bfloat162*>(&lw[q]);
                float2 fh = __bfloat1622float2(hb);
                float2 fl = __bfloat1622float2(lb);
                float f0 = c * (fh.x + fl.x);
                float f1 = c * (fh.y + fl.y);
                __nv_bfloat162 nh = __floats2bfloat162_rn(f0, f1);
                float2 nhf = __bfloat1622float2(nh);
                __nv_bfloat162 nl = __floats2bfloat162_rn(f0 - nhf.x, f1 - nhf.y);
                oh[q] = *reinterpret_cast<uint32_t*>(&nh);
                ol[q] = *reinterpret_cast<uint32_t*>(&nl);
            }
            *reinterpret_cast<uint4*>(bS_h + r * ROWW + seg * 4) =
                make_uint4(oh[0], oh[1], oh[2], oh[3]);
            *reinterpret_cast<uint4*>(bS_l + r * ROWW + seg * 4) =
                make_uint4(ol[0], ol[1], ol[2], ol[3]);
        }
    } else {
#pragma unroll
        for (int it = 0; it < 10; it++) {
            int idx = t + 256 * it, r = idx >> 4, seg = idx & 15;
            size_t g = (size_t)r * BATCH + k0 + seg * 8;
            *reinterpret_cast<uint4*>(bS_h + r * ROWW + seg * 4) =
                *reinterpret_cast<const uint4*>(g_vTh + g);
            *reinterpret_cast<uint4*>(bS_l + r * ROWW + seg * 4) =
                *reinterpret_cast<const uint4*>(g_vTl + g);
        }
    }
    __syncthreads();

    int wid = t >> 5, lane = t & 31;
    int wm = wid & 3, wn = wid >> 2;               // 4 m-warps x 2 n-warps
    int qrow = lane >> 2, qcol = lane & 3;

    float acc[2][10][4];
#pragma unroll
    for (int mt = 0; mt < 2; mt++)
#pragma unroll
        for (int nt = 0; nt < 10; nt++)
#pragma unroll
            for (int j = 0; j < 4; j++) acc[mt][nt][j] = 0.0f;

#pragma unroll
    for (int ks = 0; ks < 8; ks++) {
        uint32_t bh[10][2], bl[10][2];
#pragma unroll
        for (int nt = 0; nt < 10; nt++) {
            int w = (wn * 80 + nt * 8 + qrow) * ROWW + ks * 8 + qcol;
            bh[nt][0] = bS_h[w]; bh[nt][1] = bS_h[w + 4];
            bl[nt][0] = bS_l[w]; bl[nt][1] = bS_l[w + 4];
        }
#pragma unroll
        for (int mt = 0; mt < 2; mt++) {
            int w = (wm * 32 + mt * 16 + qrow) * ROWW + ks * 8 + qcol;
            uint32_t ah0 = aS_h[w], ah1 = aS_h[w + 8 * ROWW];
            uint32_t ah2 = aS_h[w + 4], ah3 = aS_h[w + 8 * ROWW + 4];
            uint32_t al0 = aS_l[w], al1 = aS_l[w + 8 * ROWW];
            uint32_t al2 = aS_l[w + 4], al3 = aS_l[w + 8 * ROWW + 4];
#pragma unroll
            for (int nt = 0; nt < 10; nt++) {
                MMA_BF16(acc[mt][nt], ah0, ah1, ah2, ah3, bh[nt][0], bh[nt][1]); // hi*hi
                MMA_BF16(acc[mt][nt], ah0, ah1, ah2, ah3, bl[nt][0], bl[nt][1]); // hi*lo
                MMA_BF16(acc[mt][nt], al0, al1, al2, al3, bh[nt][0], bh[nt][1]); // lo*hi
            }
        }
    }

#pragma unroll
    for (int mt = 0; mt < 2; mt++) {
        int row = arow0 + wm * 32 + mt * 16 + qrow;
#pragma unroll
        for (int nt = 0; nt < 10; nt++) {
            int col = wn * 80 + nt * 8 + qcol * 2;
            *reinterpret_cast<float2*>(outp + (size_t)row * 160 + col) =
                make_float2(acc[mt][nt][0], acc[mt][nt][1]);
            *reinterpret_cast<float2*>(outp + (size_t)(row + 8) * 160 + col) =
                make_float2(acc[mt][nt][2], acc[mt][nt][3]);
        }
    }
}

// ---------------------------------------------------------------------------
// Split-K reduce stage 1 (float4): 72 -> 8 partials. grid (40,8) x 256.
__global__ void k_red1() {
    int e4 = blockIdx.x * 256 + threadIdx.x;       // < 10240
    int g = blockIdx.y;
    const float4* sp = reinterpret_cast<const float4*>(g_spart);
    float4 a = make_float4(0.f, 0.f, 0.f, 0.f);
#pragma unroll
    for (int p = 0; p < 9; p++) {
        float4 v = sp[(size_t)(g * 9 + p) * 10240 + e4];
        a.x += v.x; a.y += v.y; a.z += v.z; a.w += v.w;
    }
    reinterpret_cast<float4*>(g_spart2)[(size_t)g * 10240 + e4] = a;
}

// Stage 2 + squash (+ v^T bf16 split for the next M-GEMM). grid 40 x 256.
__global__ void k_red2(float* dst, int writeVT) {
    int t4 = blockIdx.x * 256 + threadIdx.x;       // < 10240
    const float4* sp = reinterpret_cast<const float4*>(g_spart2);
    float4 a = make_float4(0.f, 0.f, 0.f, 0.f);
#pragma unroll
    for (int p = 0; p < 8; p++) {
        float4 v = sp[(size_t)p * 10240 + t4];
        a.x += v.x; a.y += v.y; a.z += v.z; a.w += v.w;
    }
    float sq = a.x * a.x + a.y * a.y + a.z * a.z + a.w * a.w;
    sq += __shfl_xor_sync(0xffffffffu, sq, 1);     // 4 lanes = 16 u's
    sq += __shfl_xor_sync(0xffffffffu, sq, 2);
    float m = sq / ((1.0f + sq) * sqrtf(sq + 1e-9f));
    float4 v = make_float4(a.x * m, a.y * m, a.z * m, a.w * m);
    if (writeVT) {
        int elem0 = t4 * 4;
        int b = elem0 / 160, ou0 = elem0 - b * 160;
        float vv[4] = {v.x, v.y, v.z, v.w};
#pragma unroll
        for (int j = 0; j < 4; j++) {
            __nv_bfloat16 h = __float2bfloat16(vv[j]);
            size_t o = (size_t)(ou0 + j) * BATCH + b;
            g_vTh[o] = h;
            g_vTl[o] = __float2bfloat16(vv[j] - __bfloat162float(h));
        }
    } else {
        reinterpret_cast<float4*>(dst)[t4] = v;
    }
}

// ---------------------------------------------------------------------------
// b[i,o] += (1/B)*sum_{k,u} W[i][ou][k]*(m0+m1)[ik][ou]; fused softmax -> c.
// W read in NATIVE layout: thread t=ou does 2 coalesced float4 loads (32B).
__global__ __launch_bounds__(160) void k_bdot(const float* __restrict__ W) {
    __shared__ float so[10];
    int i = blockIdx.x;
    int t = threadIdx.x;                            // = ou
    const float4* Wp = reinterpret_cast<const float4*>(W + (size_t)i * 1280 + t * 8);
    float4 w0 = __ldg(Wp), w1 = __ldg(Wp + 1);
    float wk[8] = {w0.x, w0.y, w0.z, w0.w, w1.x, w1.y, w1.z, w1.w};
    const float* mp = g_mpart + (size_t)(i * 8) * 160 + t;
    float acc = 0.0f;
#pragma unroll
    for (int k = 0; k < 8; k++)
        acc += wk[k] * (__ldg(mp + k * 160) + __ldg(mp + MO + k * 160));
#pragma unroll
    for (int off = 8; off; off >>= 1) acc += __shfl_xor_sync(0xffffffffu, acc, off, 16);
    if ((t & 15) == 0) so[t >> 4] = acc;
    __syncthreads();
    float bn = -1e30f;
    if (t < 10) {
        bn = g_blog[i * 10 + t] + so[t] * (1.0f / BATCH);
        g_blog[i * 10 + t] = bn;
    }
    float m = bn;
#pragma unroll
    for (int off = 8; off; off >>= 1) m = fmaxf(m, __shfl_xor_sync(0xffffffffu, m, off, 16));
    float e = (t < 10) ? __expf(bn - m) : 0.0f;
    float s = e;
#pragma unroll
    for (int off = 8; off; off >>= 1) s += __shfl_xor_sync(0xffffffffu, s, off, 16);
    if (t < 10) g_c[i * 10 + t] = e / s;
}

// ---------------------------------------------------------------------------
extern "C" void kernel_launch(void* const* d_in, const int* in_sizes, int n_in,
                              void* d_out, int out_size) {
    const float* inp = (const float*)d_in[0];
    const float* W   = (const float*)d_in[1];
    if (in_sizes[0] == IN_CH * OUT_CH * OUT_U * 8) {       // defensive order check
        W = (const float*)d_in[0];
        inp = (const float*)d_in[1];
    }
    float* out = (float*)d_out;

    cudaFuncSetAttribute(k_mma, cudaFuncAttributeMaxDynamicSharedMemorySize, SM_TOTAL);

    dim3 gg(KSPLIT, 2), gt(NIK / 32, BATCH / 32), gr1(40, 8);

    k_init<<<45, 256>>>();
    k_splitW<<<MO / 256, 256>>>(W);
    k_split_x<<<gt, 256>>>(inp);
    // epoch 1 (c = 0.1 uniform via g_c init)
    k_mma<<<gg, 256, SM_TOTAL>>>(0);
    k_red1<<<gr1, 256>>>();
    k_red2<<<40, 256>>>(nullptr, 1);                       // v0 -> vT
    k_mma<<<gg, 256, SM_TOTAL>>>(1);
    k_bdot<<<IN_CH, 160>>>(W);                             // b1, c1
    // epoch 2
    k_mma<<<gg, 256, SM_TOTAL>>>(0);
    k_red1<<<gr1, 256>>>();
    k_red2<<<40, 256>>>(nullptr, 1);                       // v1 -> vT
    k_mma<<<gg, 256, SM_TOTAL>>>(1);
    k_bdot<<<IN_CH, 160>>>(W);                             // b2, c2
    // epoch 3
    k_mma<<<gg, 256, SM_TOTAL>>>(0);
    k_red1<<<gr1, 256>>>();
    k_red2<<<40, 256>>>(out, 0);                           // v2 -> output
}